// round 2
// baseline (speedup 1.0000x reference)
#include <cuda_runtime.h>
#include <cuda_bf16.h>
#include <math.h>

// ---------------- problem constants ----------------
#define BATCH 2
#define SEQ   2048
#define TOK   4096          // BATCH*SEQ
#define HID   2048          // H
#define NEXP  32            // E
#define NGRP  8             // G
#define EPG   4             // E/G
#define TKG   4             // topk_group
#define TOPK  8             // K
#define IDIM  1024          // I
#define SDIM  2048          // SI
#define NROW  32768         // TOK*TOPK
#define ROUTED_SCALE 2.5f

// ---------------- scratch (device globals; no allocations allowed) ----------
__device__ int   g_tkidx[NROW];
__device__ float g_tkw[NROW];
__device__ int   g_counts[NEXP];
__device__ int   g_offsets[NEXP];
__device__ int   g_cursor[NEXP];
__device__ int   g_row_token[NROW];   // grouped row p -> token id
__device__ int   g_inv[NROW];         // (t*K+k) -> grouped row p

__device__ float g_gate[NROW * IDIM];     // 134 MB (reused as act)
__device__ float g_up  [NROW * IDIM];     // 134 MB
__device__ float g_down[NROW * HID];      // 268 MB
__device__ float g_sg  [TOK * SDIM];      // 33.5 MB (reused as shared act)
__device__ float g_su  [TOK * SDIM];      // 33.5 MB

// ---------------- router: logits + grouped top-k ----------------
__global__ void __launch_bounds__(128)
router_kernel(const float* __restrict__ x,
              const float* __restrict__ rw,
              const float* __restrict__ rbias)
{
    int t = blockIdx.x;
    __shared__ float sx[HID];
    __shared__ float spart[4][NEXP];
    __shared__ float slog[NEXP];
    int tid = threadIdx.x;                 // 128 threads
    const float4* xr = (const float4*)(x + (size_t)t * HID);
    float4* sxv = (float4*)sx;
    for (int i = tid; i < HID / 4; i += 128) sxv[i] = xr[i];
    __syncthreads();

    int w = tid >> 5, lane = tid & 31;
    float acc = 0.f;
    int h0 = w * (HID / 4);
    #pragma unroll 4
    for (int h = h0; h < h0 + HID / 4; ++h)
        acc = fmaf(sx[h], rw[h * NEXP + lane], acc);   // coalesced row read
    spart[w][lane] = acc;
    __syncthreads();
    if (tid < NEXP)
        slog[tid] = spart[0][tid] + spart[1][tid] + spart[2][tid] + spart[3][tid];
    __syncthreads();

    if (tid == 0) {
        float sc[NEXP], sb[NEXP];
        #pragma unroll
        for (int e = 0; e < NEXP; ++e) {
            float s = 1.f / (1.f + expf(-slog[e]));
            sc[e] = s;
            sb[e] = s + rbias[e];
        }
        // group scores = sum of top-2 within each group of 4
        float gs[NGRP];
        #pragma unroll
        for (int g = 0; g < NGRP; ++g) {
            float m1 = -1e30f, m2 = -1e30f;
            #pragma unroll
            for (int j = 0; j < EPG; ++j) {
                float v = sb[g * EPG + j];
                if (v > m1) { m2 = m1; m1 = v; }
                else if (v > m2) { m2 = v; }
            }
            gs[g] = m1 + m2;
        }
        // keep top TKG groups (first-index on ties, like jax top_k)
        bool keep[NGRP];
        #pragma unroll
        for (int g = 0; g < NGRP; ++g) keep[g] = false;
        for (int r = 0; r < TKG; ++r) {
            int bi = -1; float bv = -1e30f;
            for (int g = 0; g < NGRP; ++g)
                if (!keep[g] && gs[g] > bv) { bv = gs[g]; bi = g; }
            keep[bi] = true;
        }
        float masked[NEXP];
        #pragma unroll
        for (int e = 0; e < NEXP; ++e)
            masked[e] = keep[e >> 2] ? sb[e] : 0.0f;
        // top-K experts
        int idx[TOPK];
        for (int r = 0; r < TOPK; ++r) {
            int bi = 0; float bv = -1e30f;
            for (int e = 0; e < NEXP; ++e)
                if (masked[e] > bv) { bv = masked[e]; bi = e; }
            masked[bi] = -1e30f;
            idx[r] = bi;
        }
        float wsum = 0.f, wv[TOPK];
        #pragma unroll
        for (int r = 0; r < TOPK; ++r) { wv[r] = sc[idx[r]]; wsum += wv[r]; }
        float inv = ROUTED_SCALE / wsum;
        #pragma unroll
        for (int r = 0; r < TOPK; ++r) {
            g_tkidx[t * TOPK + r] = idx[r];
            g_tkw  [t * TOPK + r] = wv[r] * inv;
        }
    }
}

// ---------------- dispatch build ----------------
__global__ void zero_counts_kernel()
{
    int i = threadIdx.x;
    if (i < NEXP) { g_counts[i] = 0; g_cursor[i] = 0; }
}

__global__ void hist_kernel()
{
    int i = blockIdx.x * blockDim.x + threadIdx.x;
    if (i < NROW) atomicAdd(&g_counts[g_tkidx[i]], 1);
}

__global__ void scan_kernel()
{
    if (threadIdx.x == 0) {
        int acc = 0;
        for (int e = 0; e < NEXP; ++e) { g_offsets[e] = acc; acc += g_counts[e]; }
    }
}

__global__ void scatter_kernel()
{
    int i = blockIdx.x * blockDim.x + threadIdx.x;
    if (i < NROW) {
        int e = g_tkidx[i];
        int pos = g_offsets[e] + atomicAdd(&g_cursor[e], 1);
        g_row_token[pos] = i / TOPK;
        g_inv[i] = pos;
    }
}

// ---------------- SGEMM: 128x128x8 double-buffered, 8x8 per-thread ---------
#define BM 128
#define BN 128
#define BK 8
#define TM 8
#define TN 8
#define APAD 4

__global__ void __launch_bounds__(256, 2)
sgemm_kernel(const float* __restrict__ A, const float* __restrict__ B0,
             float* __restrict__ C,
             int N, int Kd, int lda,
             int grouped, int gather, int Mtotal)
{
    __shared__ float As[2][BK][BM + APAD];
    __shared__ float Bs[2][BK][BN];

    int e = blockIdx.z;
    int off, cnt;
    if (grouped) { off = g_offsets[e]; cnt = g_counts[e]; }
    else         { off = 0;            cnt = Mtotal; }
    int mtile = blockIdx.y * BM;
    if (mtile >= cnt) return;

    const float* B = B0 + (size_t)e * Kd * N;
    int n0 = blockIdx.x * BN;
    int tid = threadIdx.x;

    // A load: thread -> (row, 4 cols)
    int arow = tid >> 1;
    int acol = (tid & 1) * 4;
    int lr = mtile + arow;
    bool avalid = (lr < cnt);
    const float* Aptr = nullptr;
    if (avalid) {
        int p = off + lr;
        int arg = gather ? g_row_token[p] : p;
        Aptr = A + (size_t)arg * lda + acol;
    }
    // B load: thread -> (k-row, 4 cols)
    int brow = tid >> 5;
    int bcol = (tid & 31) * 4;
    const float* Bptr = B + (size_t)brow * N + n0 + bcol;
    const size_t bstep = (size_t)BK * N;

    const float4 f4z = make_float4(0.f, 0.f, 0.f, 0.f);

    // preload tile 0
    float4 av = avalid ? *(const float4*)Aptr : f4z;
    float4 bv = *(const float4*)Bptr;
    As[0][acol + 0][arow] = av.x;
    As[0][acol + 1][arow] = av.y;
    As[0][acol + 2][arow] = av.z;
    As[0][acol + 3][arow] = av.w;
    *(float4*)&Bs[0][brow][bcol] = bv;
    __syncthreads();

    float acc[TM][TN];
    #pragma unroll
    for (int i = 0; i < TM; ++i)
        #pragma unroll
        for (int j = 0; j < TN; ++j) acc[i][j] = 0.f;

    int ty = tid >> 4, tx = tid & 15;
    int numK = Kd / BK;
    int buf = 0;

    for (int t = 0; t < numK; ++t) {
        float4 na = f4z, nb = f4z;
        bool has_next = (t + 1 < numK);
        if (has_next) {
            if (avalid) na = *(const float4*)(Aptr + (size_t)(t + 1) * BK);
            nb = *(const float4*)(Bptr + (size_t)(t + 1) * bstep);
        }
        #pragma unroll
        for (int kk = 0; kk < BK; ++kk) {
            float a[TM], b[TN];
            const float4* ap = (const float4*)&As[buf][kk][ty * TM];
            float4 a0 = ap[0], a1 = ap[1];
            const float4* bp = (const float4*)&Bs[buf][kk][tx * TN];
            float4 b0 = bp[0], b1 = bp[1];
            a[0]=a0.x; a[1]=a0.y; a[2]=a0.z; a[3]=a0.w;
            a[4]=a1.x; a[5]=a1.y; a[6]=a1.z; a[7]=a1.w;
            b[0]=b0.x; b[1]=b0.y; b[2]=b0.z; b[3]=b0.w;
            b[4]=b1.x; b[5]=b1.y; b[6]=b1.z; b[7]=b1.w;
            #pragma unroll
            for (int i = 0; i < TM; ++i)
                #pragma unroll
                for (int j = 0; j < TN; ++j)
                    acc[i][j] = fmaf(a[i], b[j], acc[i][j]);
        }
        if (has_next) {
            int nbuf = buf ^ 1;
            As[nbuf][acol + 0][arow] = na.x;
            As[nbuf][acol + 1][arow] = na.y;
            As[nbuf][acol + 2][arow] = na.z;
            As[nbuf][acol + 3][arow] = na.w;
            *(float4*)&Bs[nbuf][brow][bcol] = nb;
            __syncthreads();
            buf = nbuf;
        }
    }

    #pragma unroll
    for (int i = 0; i < TM; ++i) {
        int lrr = mtile + ty * TM + i;
        if (lrr < cnt) {
            float* cp = C + (size_t)(off + lrr) * N + n0 + tx * TN;
            float4 v0 = make_float4(acc[i][0], acc[i][1], acc[i][2], acc[i][3]);
            float4 v1 = make_float4(acc[i][4], acc[i][5], acc[i][6], acc[i][7]);
            *(float4*)cp = v0;
            *(float4*)(cp + 4) = v1;
        }
    }
}

// ---------------- SwiGLU elementwise: g = silu(g) * u ----------------
__global__ void silu_mul_kernel(float* __restrict__ g, const float* __restrict__ u,
                                long n4)
{
    long i = (long)blockIdx.x * blockDim.x + threadIdx.x;
    long stride = (long)gridDim.x * blockDim.x;
    float4* gv = (float4*)g;
    const float4* uv = (const float4*)u;
    for (; i < n4; i += stride) {
        float4 gg = gv[i];
        float4 uu = uv[i];
        gg.x = gg.x / (1.f + __expf(-gg.x)) * uu.x;
        gg.y = gg.y / (1.f + __expf(-gg.y)) * uu.y;
        gg.z = gg.z / (1.f + __expf(-gg.z)) * uu.z;
        gg.w = gg.w / (1.f + __expf(-gg.w)) * uu.w;
        gv[i] = gg;
    }
}

// ---------------- combine: out[t] += sum_k w[t,k] * down[inv[t,k]] ---------
__global__ void combine_kernel(const float* __restrict__ down, float* __restrict__ out)
{
    int t = blockIdx.x;
    int tid = threadIdx.x;   // 256
    int   pidx[TOPK];
    float pw[TOPK];
    #pragma unroll
    for (int k = 0; k < TOPK; ++k) {
        pidx[k] = g_inv[t * TOPK + k];
        pw[k]   = g_tkw[t * TOPK + k];
    }
    const int H4 = HID / 4;   // 512
    float4* ov = (float4*)out;
    const float4* dv = (const float4*)down;
    for (int i = tid; i < H4; i += 256) {
        float4 o = ov[(size_t)t * H4 + i];
        #pragma unroll
        for (int k = 0; k < TOPK; ++k) {
            float4 v = dv[(size_t)pidx[k] * H4 + i];
            float w = pw[k];
            o.x = fmaf(w, v.x, o.x);
            o.y = fmaf(w, v.y, o.y);
            o.z = fmaf(w, v.z, o.z);
            o.w = fmaf(w, v.w, o.w);
        }
        ov[(size_t)t * H4 + i] = o;
    }
}

// ---------------- launch ----------------
static float* symf(const void* sym) {
    void* p = nullptr;
    cudaGetSymbolAddress(&p, sym);
    return (float*)p;
}

extern "C" void kernel_launch(void* const* d_in, const int* in_sizes, int n_in,
                              void* d_out, int out_size)
{
    const float* x       = (const float*)d_in[0];  // [B,S,H]
    const float* rw      = (const float*)d_in[1];  // [H,E]
    const float* rbias   = (const float*)d_in[2];  // [E]
    const float* w_gate  = (const float*)d_in[3];  // [E,H,I]
    const float* w_up    = (const float*)d_in[4];  // [E,H,I]
    const float* w_down  = (const float*)d_in[5];  // [E,I,H]
    const float* sw_gate = (const float*)d_in[6];  // [H,SI]
    const float* sw_up   = (const float*)d_in[7];  // [H,SI]
    const float* sw_down = (const float*)d_in[8];  // [SI,H]
    float* out = (float*)d_out;

    float* p_gate = symf(g_gate);
    float* p_up   = symf(g_up);
    float* p_down = symf(g_down);
    float* p_sg   = symf(g_sg);
    float* p_su   = symf(g_su);

    // 1) router + top-k
    router_kernel<<<TOK, 128>>>(x, rw, rbias);

    // 2) dispatch build
    zero_counts_kernel<<<1, 32>>>();
    hist_kernel<<<NROW / 256, 256>>>();
    scan_kernel<<<1, 1>>>();
    scatter_kernel<<<NROW / 256, 256>>>();

    // 3) routed experts: gate / up grouped GEMMs (A gathered from x)
    dim3 blk(256);
    dim3 grd_gu(IDIM / BN, TOK / BM, NEXP);           // (8, 32, 32)
    sgemm_kernel<<<grd_gu, blk>>>(x, w_gate, p_gate, IDIM, HID, HID, 1, 1, 0);
    sgemm_kernel<<<grd_gu, blk>>>(x, w_up,   p_up,   IDIM, HID, HID, 1, 1, 0);

    // 4) SwiGLU (in place into g_gate)
    silu_mul_kernel<<<2048, 256>>>(p_gate, p_up, (long)NROW * IDIM / 4);

    // 5) down grouped GEMM
    dim3 grd_dn(HID / BN, TOK / BM, NEXP);            // (16, 32, 32)
    sgemm_kernel<<<grd_dn, blk>>>(p_gate, w_down, p_down, HID, IDIM, IDIM, 1, 0, 0);

    // 6) shared expert
    dim3 grd_sh(SDIM / BN, TOK / BM, 1);              // (16, 32, 1)
    sgemm_kernel<<<grd_sh, blk>>>(x, sw_gate, p_sg, SDIM, HID, HID, 0, 0, TOK);
    sgemm_kernel<<<grd_sh, blk>>>(x, sw_up,   p_su, SDIM, HID, HID, 0, 0, TOK);
    silu_mul_kernel<<<2048, 256>>>(p_sg, p_su, (long)TOK * SDIM / 4);
    dim3 grd_sd(HID / BN, TOK / BM, 1);               // (16, 32, 1)
    sgemm_kernel<<<grd_sd, blk>>>(p_sg, sw_down, out, HID, SDIM, SDIM, 0, 0, TOK);

    // 7) weighted combine of routed outputs into d_out
    combine_kernel<<<TOK, 256>>>(p_down, out);
}

// round 4
// speedup vs baseline: 2.2077x; 2.2077x over previous
#include <cuda_runtime.h>
#include <cuda_bf16.h>
#include <math.h>
#include <stdint.h>

// ---------------- problem constants ----------------
#define TOK   4096
#define HID   2048
#define NEXP  32
#define NGRP  8
#define EPG   4
#define TKG   4
#define TOPK  8
#define IDIM  1024
#define SDIM  2048
#define NROW  32768
#define ROUTED_SCALE 2.5f

// ---------------- scratch ----------------
__device__ int   g_tkidx[NROW];
__device__ float g_tkw[NROW];
__device__ int   g_counts[NEXP];
__device__ int   g_offsets[NEXP];
__device__ int   g_cursor[NEXP];
__device__ int   g_row_token[NROW];
__device__ int   g_inv[NROW];

__device__ float g_gate[NROW * IDIM];
__device__ float g_up  [NROW * IDIM];
__device__ float g_down[NROW * HID];
__device__ float g_sg  [TOK * SDIM];
__device__ float g_su  [TOK * SDIM];

// ---------------- router ----------------
__global__ void __launch_bounds__(128)
router_kernel(const float* __restrict__ x, const float* __restrict__ rw,
              const float* __restrict__ rbias)
{
    int t = blockIdx.x;
    __shared__ float sx[HID];
    __shared__ float spart[4][NEXP];
    __shared__ float slog[NEXP];
    int tid = threadIdx.x;
    const float4* xr = (const float4*)(x + (size_t)t * HID);
    float4* sxv = (float4*)sx;
    for (int i = tid; i < HID / 4; i += 128) sxv[i] = xr[i];
    __syncthreads();

    int w = tid >> 5, lane = tid & 31;
    float acc = 0.f;
    int h0 = w * (HID / 4);
    #pragma unroll 4
    for (int h = h0; h < h0 + HID / 4; ++h)
        acc = fmaf(sx[h], rw[h * NEXP + lane], acc);
    spart[w][lane] = acc;
    __syncthreads();
    if (tid < NEXP)
        slog[tid] = spart[0][tid] + spart[1][tid] + spart[2][tid] + spart[3][tid];
    __syncthreads();

    if (tid == 0) {
        float sc[NEXP], sb[NEXP];
        #pragma unroll
        for (int e = 0; e < NEXP; ++e) {
            float s = 1.f / (1.f + expf(-slog[e]));
            sc[e] = s;
            sb[e] = s + rbias[e];
        }
        float gs[NGRP];
        #pragma unroll
        for (int g = 0; g < NGRP; ++g) {
            float m1 = -1e30f, m2 = -1e30f;
            #pragma unroll
            for (int j = 0; j < EPG; ++j) {
                float v = sb[g * EPG + j];
                if (v > m1) { m2 = m1; m1 = v; }
                else if (v > m2) { m2 = v; }
            }
            gs[g] = m1 + m2;
        }
        bool keep[NGRP];
        #pragma unroll
        for (int g = 0; g < NGRP; ++g) keep[g] = false;
        for (int r = 0; r < TKG; ++r) {
            int bi = -1; float bv = -1e30f;
            for (int g = 0; g < NGRP; ++g)
                if (!keep[g] && gs[g] > bv) { bv = gs[g]; bi = g; }
            keep[bi] = true;
        }
        float masked[NEXP];
        #pragma unroll
        for (int e = 0; e < NEXP; ++e)
            masked[e] = keep[e >> 2] ? sb[e] : 0.0f;
        int idx[TOPK];
        for (int r = 0; r < TOPK; ++r) {
            int bi = 0; float bv = -1e30f;
            for (int e = 0; e < NEXP; ++e)
                if (masked[e] > bv) { bv = masked[e]; bi = e; }
            masked[bi] = -1e30f;
            idx[r] = bi;
        }
        float wsum = 0.f, wv[TOPK];
        #pragma unroll
        for (int r = 0; r < TOPK; ++r) { wv[r] = sc[idx[r]]; wsum += wv[r]; }
        float inv = ROUTED_SCALE / wsum;
        #pragma unroll
        for (int r = 0; r < TOPK; ++r) {
            g_tkidx[t * TOPK + r] = idx[r];
            g_tkw  [t * TOPK + r] = wv[r] * inv;
        }
    }
}

// ---------------- dispatch build ----------------
__global__ void zero_counts_kernel()
{
    int i = threadIdx.x;
    if (i < NEXP) { g_counts[i] = 0; g_cursor[i] = 0; }
}
__global__ void hist_kernel()
{
    int i = blockIdx.x * blockDim.x + threadIdx.x;
    if (i < NROW) atomicAdd(&g_counts[g_tkidx[i]], 1);
}
__global__ void scan_kernel()
{
    if (threadIdx.x == 0) {
        int acc = 0;
        for (int e = 0; e < NEXP; ++e) { g_offsets[e] = acc; acc += g_counts[e]; }
    }
}
__global__ void scatter_kernel()
{
    int i = blockIdx.x * blockDim.x + threadIdx.x;
    if (i < NROW) {
        int e = g_tkidx[i];
        int pos = g_offsets[e] + atomicAdd(&g_cursor[e], 1);
        g_row_token[pos] = i / TOPK;
        g_inv[i] = pos;
    }
}

// ---------------- tf32 helpers ----------------
__device__ __forceinline__ uint32_t f2tf(float f) {
    uint32_t r;
    asm("cvt.rna.tf32.f32 %0, %1;" : "=r"(r) : "f"(f));
    return r;
}
__device__ __forceinline__ void mma_tf32(float* d, const uint32_t* a, const uint32_t* b)
{
    asm volatile(
        "mma.sync.aligned.m16n8k8.row.col.f32.tf32.tf32.f32 "
        "{%0,%1,%2,%3}, {%4,%5,%6,%7}, {%8,%9}, {%0,%1,%2,%3};\n"
        : "+f"(d[0]), "+f"(d[1]), "+f"(d[2]), "+f"(d[3])
        : "r"(a[0]), "r"(a[1]), "r"(a[2]), "r"(a[3]), "r"(b[0]), "r"(b[1]));
}

// ---------------- tf32 tensor-core GEMM ----------------
// C[m][n] = sum_k A[m][k] * B[k][n]; A row-major [M][Kd], B row-major [Kd][N]
// (B's row-major [K][N] == mma's col-major k x n operand)
// Block tile 128x128, BK=32, double-buffered smem, 8 warps of 32x64 tiles.
#define AS_STRIDE 36
#define BS_STRIDE 132
#define AS_BUF (128 * AS_STRIDE)      // 4608
#define BS_BUF (32 * BS_STRIDE)       // 4224
#define GEMM_SMEM_U32 (128 + 2 * AS_BUF + 2 * BS_BUF)   // 17792 u32 = 71168 B

__global__ void __launch_bounds__(256)
tmma_kernel(const float* __restrict__ A, const float* __restrict__ B0,
            float* __restrict__ C,
            int N, int Kd, int grouped, int gather, int Mtotal)
{
    extern __shared__ uint32_t smu[];
    int* sArow = (int*)smu;
    uint32_t* Asb = smu + 128;
    uint32_t* Bsb = smu + 128 + 2 * AS_BUF;
#define AS(b, m, k) Asb[(b) * AS_BUF + (m) * AS_STRIDE + (k)]
#define BS(b, k, n) Bsb[(b) * BS_BUF + (k) * BS_STRIDE + (n)]

    int tid = threadIdx.x;
    int e = blockIdx.z;
    int off, cnt;
    if (grouped) { off = g_offsets[e]; cnt = g_counts[e]; }
    else         { off = 0;            cnt = Mtotal; }
    int mtile = blockIdx.y * 128;
    if (mtile >= cnt) return;
    int n0 = blockIdx.x * 128;

    if (tid < 128) {
        int lr = mtile + tid;
        if (lr >= cnt) lr = cnt - 1;
        int p = off + lr;
        sArow[tid] = gather ? g_row_token[p] : p;
    }
    __syncthreads();

    const float* Bg = B0 + (size_t)e * Kd * N + n0;

    // A: thread -> row=tid>>1, 16-col segment (tid&1)*16, 4 float4
    int arow_l = tid >> 1;
    int aseg = (tid & 1) * 16;
    const float* Aptr = A + (size_t)sArow[arow_l] * Kd + aseg;
    // B: 4 passes, row=(tid>>5)+8p, col4=(tid&31)
    int bkrow = tid >> 5;
    int bcol = (tid & 31) * 4;

    float4 ra[4], rb[4];
    // prologue: tile 0
    #pragma unroll
    for (int j = 0; j < 4; ++j) {
        ra[j] = *(const float4*)(Aptr + j * 4);
        rb[j] = *(const float4*)(Bg + (size_t)(bkrow + 8 * j) * N + bcol);
    }
    #pragma unroll
    for (int j = 0; j < 4; ++j) {
        uint4 ua = make_uint4(f2tf(ra[j].x), f2tf(ra[j].y), f2tf(ra[j].z), f2tf(ra[j].w));
        *(uint4*)&AS(0, arow_l, aseg + j * 4) = ua;
        uint4 ub = make_uint4(f2tf(rb[j].x), f2tf(rb[j].y), f2tf(rb[j].z), f2tf(rb[j].w));
        *(uint4*)&BS(0, bkrow + 8 * j, bcol) = ub;
    }
    __syncthreads();

    int wid = tid >> 5, lane = tid & 31;
    int wm = wid >> 1, wn = wid & 1;           // warp tile: rows wm*32, cols wn*64
    int g = lane >> 2, tg = lane & 3;

    float acc[2][8][4];
    #pragma unroll
    for (int mi = 0; mi < 2; ++mi)
        #pragma unroll
        for (int ni = 0; ni < 8; ++ni)
            #pragma unroll
            for (int c = 0; c < 4; ++c) acc[mi][ni][c] = 0.f;

    int numK = Kd >> 5;
    for (int t = 0; t < numK; ++t) {
        bool has_next = (t + 1 < numK);
        if (has_next) {
            int ko = (t + 1) << 5;
            #pragma unroll
            for (int j = 0; j < 4; ++j) {
                ra[j] = *(const float4*)(Aptr + ko + j * 4);
                rb[j] = *(const float4*)(Bg + (size_t)(ko + bkrow + 8 * j) * N + bcol);
            }
        }
        int buf = t & 1;
        #pragma unroll
        for (int kk = 0; kk < 4; ++kk) {
            int k8 = kk * 8;
            uint32_t af[2][4];
            #pragma unroll
            for (int mi = 0; mi < 2; ++mi) {
                int r0 = wm * 32 + mi * 16 + g;
                af[mi][0] = AS(buf, r0,     k8 + tg);
                af[mi][1] = AS(buf, r0 + 8, k8 + tg);
                af[mi][2] = AS(buf, r0,     k8 + tg + 4);
                af[mi][3] = AS(buf, r0 + 8, k8 + tg + 4);
            }
            uint32_t bf[8][2];
            #pragma unroll
            for (int ni = 0; ni < 8; ++ni) {
                int nn = wn * 64 + ni * 8 + g;
                bf[ni][0] = BS(buf, k8 + tg,     nn);
                bf[ni][1] = BS(buf, k8 + tg + 4, nn);
            }
            #pragma unroll
            for (int mi = 0; mi < 2; ++mi)
                #pragma unroll
                for (int ni = 0; ni < 8; ++ni)
                    mma_tf32(acc[mi][ni], af[mi], bf[ni]);
        }
        if (has_next) {
            int nbuf = buf ^ 1;
            #pragma unroll
            for (int j = 0; j < 4; ++j) {
                uint4 ua = make_uint4(f2tf(ra[j].x), f2tf(ra[j].y), f2tf(ra[j].z), f2tf(ra[j].w));
                *(uint4*)&AS(nbuf, arow_l, aseg + j * 4) = ua;
                uint4 ub = make_uint4(f2tf(rb[j].x), f2tf(rb[j].y), f2tf(rb[j].z), f2tf(rb[j].w));
                *(uint4*)&BS(nbuf, bkrow + 8 * j, bcol) = ub;
            }
            __syncthreads();
        }
    }

    // epilogue: direct float2 stores
    #pragma unroll
    for (int mi = 0; mi < 2; ++mi) {
        int lr0 = mtile + wm * 32 + mi * 16 + g;
        #pragma unroll
        for (int ni = 0; ni < 8; ++ni) {
            int col = n0 + wn * 64 + ni * 8 + tg * 2;
            if (lr0 < cnt)
                *(float2*)(C + (size_t)(off + lr0) * N + col) =
                    make_float2(acc[mi][ni][0], acc[mi][ni][1]);
            if (lr0 + 8 < cnt)
                *(float2*)(C + (size_t)(off + lr0 + 8) * N + col) =
                    make_float2(acc[mi][ni][2], acc[mi][ni][3]);
        }
    }
#undef AS
#undef BS
}

// ---------------- SwiGLU elementwise: g = silu(g) * u ----------------
__global__ void silu_mul_kernel(float* __restrict__ g, const float* __restrict__ u,
                                long n4)
{
    long i = (long)blockIdx.x * blockDim.x + threadIdx.x;
    long stride = (long)gridDim.x * blockDim.x;
    float4* gv = (float4*)g;
    const float4* uv = (const float4*)u;
    for (; i < n4; i += stride) {
        float4 gg = gv[i];
        float4 uu = uv[i];
        gg.x = gg.x / (1.f + __expf(-gg.x)) * uu.x;
        gg.y = gg.y / (1.f + __expf(-gg.y)) * uu.y;
        gg.z = gg.z / (1.f + __expf(-gg.z)) * uu.z;
        gg.w = gg.w / (1.f + __expf(-gg.w)) * uu.w;
        gv[i] = gg;
    }
}

// ---------------- combine ----------------
__global__ void combine_kernel(const float* __restrict__ down, float* __restrict__ out)
{
    int t = blockIdx.x;
    int tid = threadIdx.x;
    int   pidx[TOPK];
    float pw[TOPK];
    #pragma unroll
    for (int k = 0; k < TOPK; ++k) {
        pidx[k] = g_inv[t * TOPK + k];
        pw[k]   = g_tkw[t * TOPK + k];
    }
    const int H4 = HID / 4;
    float4* ov = (float4*)out;
    const float4* dv = (const float4*)down;
    for (int i = tid; i < H4; i += 256) {
        float4 o = ov[(size_t)t * H4 + i];
        #pragma unroll
        for (int k = 0; k < TOPK; ++k) {
            float4 v = dv[(size_t)pidx[k] * H4 + i];
            float w = pw[k];
            o.x = fmaf(w, v.x, o.x);
            o.y = fmaf(w, v.y, o.y);
            o.z = fmaf(w, v.z, o.z);
            o.w = fmaf(w, v.w, o.w);
        }
        ov[(size_t)t * H4 + i] = o;
    }
}

// ---------------- launch ----------------
static float* symf(const void* sym) {
    void* p = nullptr;
    cudaGetSymbolAddress(&p, sym);
    return (float*)p;
}

extern "C" void kernel_launch(void* const* d_in, const int* in_sizes, int n_in,
                              void* d_out, int out_size)
{
    const float* x       = (const float*)d_in[0];
    const float* rw      = (const float*)d_in[1];
    const float* rbias   = (const float*)d_in[2];
    const float* w_gate  = (const float*)d_in[3];  // [E,H,I] = [E][K][N]
    const float* w_up    = (const float*)d_in[4];
    const float* w_down  = (const float*)d_in[5];  // [E,I,H] = [E][K][N]
    const float* sw_gate = (const float*)d_in[6];  // [H,SI]
    const float* sw_up   = (const float*)d_in[7];
    const float* sw_down = (const float*)d_in[8];  // [SI,H]
    float* out = (float*)d_out;

    float* p_gate = symf(g_gate);
    float* p_up   = symf(g_up);
    float* p_down = symf(g_down);
    float* p_sg   = symf(g_sg);
    float* p_su   = symf(g_su);

    static int smem_set = 0;
    if (!smem_set) {
        cudaFuncSetAttribute(tmma_kernel, cudaFuncAttributeMaxDynamicSharedMemorySize,
                             GEMM_SMEM_U32 * 4);
        smem_set = 1;
    }
    const int SMB = GEMM_SMEM_U32 * 4;

    // 1) router + dispatch
    router_kernel<<<TOK, 128>>>(x, rw, rbias);
    zero_counts_kernel<<<1, 32>>>();
    hist_kernel<<<NROW / 256, 256>>>();
    scan_kernel<<<1, 1>>>();
    scatter_kernel<<<NROW / 256, 256>>>();

    // 2) routed gate / up (A gathered from x): M=32768 grouped, N=1024, K=2048
    tmma_kernel<<<dim3(8, 32, NEXP), 256, SMB>>>(x, w_gate, p_gate, IDIM, HID, 1, 1, 0);
    tmma_kernel<<<dim3(8, 32, NEXP), 256, SMB>>>(x, w_up,   p_up,   IDIM, HID, 1, 1, 0);

    // 3) SwiGLU (in place into g_gate)
    silu_mul_kernel<<<2048, 256>>>(p_gate, p_up, (long)NROW * IDIM / 4);

    // 4) routed down: N=2048, K=1024
    tmma_kernel<<<dim3(16, 32, NEXP), 256, SMB>>>(p_gate, w_down, p_down, HID, IDIM, 1, 0, 0);

    // 5) shared expert
    tmma_kernel<<<dim3(16, 32, 1), 256, SMB>>>(x, sw_gate, p_sg, SDIM, HID, 0, 0, TOK);
    tmma_kernel<<<dim3(16, 32, 1), 256, SMB>>>(x, sw_up,   p_su, SDIM, HID, 0, 0, TOK);
    silu_mul_kernel<<<2048, 256>>>(p_sg, p_su, (long)TOK * SDIM / 4);
    tmma_kernel<<<dim3(16, 32, 1), 256, SMB>>>(p_sg, sw_down, out, HID, SDIM, 0, 0, TOK);

    // 6) weighted combine of routed outputs into d_out
    combine_kernel<<<TOK, 256>>>(p_down, out);
}

// round 6
// speedup vs baseline: 2.7549x; 1.2478x over previous
#include <cuda_runtime.h>
#include <cuda_bf16.h>
#include <math.h>
#include <stdint.h>

// ---------------- problem constants ----------------
#define TOK   4096
#define HID   2048
#define NEXP  32
#define NGRP  8
#define EPG   4
#define TKG   4
#define TOPK  8
#define IDIM  1024
#define SDIM  2048
#define NROW  32768
#define ROUTED_SCALE 2.5f

// ---------------- scratch ----------------
__device__ int   g_tkidx[NROW];
__device__ float g_tkw[NROW];
__device__ int   g_counts[NEXP];
__device__ int   g_offsets[NEXP];
__device__ int   g_row_token[NROW];
__device__ int   g_inv[NROW];

__device__ float g_gate[NROW * IDIM];
__device__ float g_up  [NROW * IDIM];
__device__ float g_down[NROW * HID];
__device__ float g_sg  [TOK * SDIM];
__device__ float g_su  [TOK * SDIM];

// ---------------- router ----------------
__global__ void __launch_bounds__(128)
router_kernel(const float* __restrict__ x, const float* __restrict__ rw,
              const float* __restrict__ rbias)
{
    int t = blockIdx.x;
    __shared__ float sx[HID];
    __shared__ float spart[4][NEXP];
    __shared__ float slog[NEXP];
    int tid = threadIdx.x;
    const float4* xr = (const float4*)(x + (size_t)t * HID);
    float4* sxv = (float4*)sx;
    for (int i = tid; i < HID / 4; i += 128) sxv[i] = xr[i];
    __syncthreads();

    int w = tid >> 5, lane = tid & 31;
    float acc = 0.f;
    int h0 = w * (HID / 4);
    #pragma unroll 4
    for (int h = h0; h < h0 + HID / 4; ++h)
        acc = fmaf(sx[h], rw[h * NEXP + lane], acc);
    spart[w][lane] = acc;
    __syncthreads();
    if (tid < NEXP)
        slog[tid] = spart[0][tid] + spart[1][tid] + spart[2][tid] + spart[3][tid];
    __syncthreads();

    if (tid == 0) {
        float sc[NEXP], sb[NEXP];
        #pragma unroll
        for (int e = 0; e < NEXP; ++e) {
            float s = 1.f / (1.f + expf(-slog[e]));
            sc[e] = s;
            sb[e] = s + rbias[e];
        }
        float gs[NGRP];
        #pragma unroll
        for (int g = 0; g < NGRP; ++g) {
            float m1 = -1e30f, m2 = -1e30f;
            #pragma unroll
            for (int j = 0; j < EPG; ++j) {
                float v = sb[g * EPG + j];
                if (v > m1) { m2 = m1; m1 = v; }
                else if (v > m2) { m2 = v; }
            }
            gs[g] = m1 + m2;
        }
        bool keep[NGRP];
        #pragma unroll
        for (int g = 0; g < NGRP; ++g) keep[g] = false;
        for (int r = 0; r < TKG; ++r) {
            int bi = -1; float bv = -1e30f;
            for (int g = 0; g < NGRP; ++g)
                if (!keep[g] && gs[g] > bv) { bv = gs[g]; bi = g; }
            keep[bi] = true;
        }
        float masked[NEXP];
        #pragma unroll
        for (int e = 0; e < NEXP; ++e)
            masked[e] = keep[e >> 2] ? sb[e] : 0.0f;
        int idx[TOPK];
        for (int r = 0; r < TOPK; ++r) {
            int bi = 0; float bv = -1e30f;
            for (int e = 0; e < NEXP; ++e)
                if (masked[e] > bv) { bv = masked[e]; bi = e; }
            masked[bi] = -1e30f;
            idx[r] = bi;
        }
        float wsum = 0.f, wv[TOPK];
        #pragma unroll
        for (int r = 0; r < TOPK; ++r) { wv[r] = sc[idx[r]]; wsum += wv[r]; }
        float inv = ROUTED_SCALE / wsum;
        #pragma unroll
        for (int r = 0; r < TOPK; ++r) {
            g_tkidx[t * TOPK + r] = idx[r];
            g_tkw  [t * TOPK + r] = wv[r] * inv;
        }
    }
}

// ---------------- fused dispatch: hist + scan + scatter (1 block) ---------
__global__ void __launch_bounds__(1024)
dispatch_kernel()
{
    __shared__ int sc[NEXP], so[NEXP], scur[NEXP];
    int tid = threadIdx.x;
    if (tid < NEXP) { sc[tid] = 0; scur[tid] = 0; }
    __syncthreads();
    for (int i = tid; i < NROW; i += 1024)
        atomicAdd(&sc[g_tkidx[i]], 1);
    __syncthreads();
    if (tid == 0) {
        int a = 0;
        #pragma unroll
        for (int e = 0; e < NEXP; ++e) { so[e] = a; a += sc[e]; }
    }
    __syncthreads();
    for (int i = tid; i < NROW; i += 1024) {
        int e = g_tkidx[i];
        int pos = so[e] + atomicAdd(&scur[e], 1);
        g_row_token[pos] = i >> 3;      // / TOPK
        g_inv[i] = pos;
    }
    if (tid < NEXP) { g_counts[tid] = sc[tid]; g_offsets[tid] = so[tid]; }
}

// ---------------- tf32 helpers ----------------
__device__ __forceinline__ uint32_t f2tf(float f) {
    uint32_t r;
    asm("cvt.rna.tf32.f32 %0, %1;" : "=r"(r) : "f"(f));
    return r;
}
__device__ __forceinline__ void mma_tf32(float* d, const uint32_t* a, const uint32_t* b)
{
    asm volatile(
        "mma.sync.aligned.m16n8k8.row.col.f32.tf32.tf32.f32 "
        "{%0,%1,%2,%3}, {%4,%5,%6,%7}, {%8,%9}, {%0,%1,%2,%3};\n"
        : "+f"(d[0]), "+f"(d[1]), "+f"(d[2]), "+f"(d[3])
        : "r"(a[0]), "r"(a[1]), "r"(a[2]), "r"(a[3]), "r"(b[0]), "r"(b[1]));
}

// ---------------- tf32 tensor-core GEMM ----------------
// C[m][n] = sum_k A[m][k] * B[k][n]; A row-major [M][Kd], B row-major [Kd][N].
// Block 256x128x32, 8 warps of 64x64. A padded (stride 36), B XOR-swizzled.
#define BM 256
#define BN 128
#define BK 32
#define AS_STRIDE 36
#define AS_BUF (BM * AS_STRIDE)      // 9216 words
#define BS_BUF (BK * BN)             // 4096 words
#define GEMM_SMEM_W (256 + 2 * AS_BUF + 2 * BS_BUF)   // 26880 words = 107520 B

__global__ void __launch_bounds__(256)
tmma_kernel(const float* __restrict__ A, const float* __restrict__ B0,
            float* __restrict__ C,
            int N, int Kd, int grouped, int gather, int Mtotal)
{
    extern __shared__ uint32_t smu[];
    int* sArow = (int*)smu;
    uint32_t* Asb = smu + 256;
    uint32_t* Bsb = smu + 256 + 2 * AS_BUF;
#define AS(b, m, k)  Asb[(b) * AS_BUF + (m) * AS_STRIDE + (k)]
#define BSW(b, k, n) Bsb[(b) * BS_BUF + (k) * BN + ((n) ^ ((((k) & 3)) << 3))]

    int tid = threadIdx.x;
    int e = blockIdx.z;
    int off, cnt;
    if (grouped) { off = g_offsets[e]; cnt = g_counts[e]; }
    else         { off = 0;            cnt = Mtotal; }
    int mtile = blockIdx.y * BM;
    if (mtile >= cnt) return;
    int n0 = blockIdx.x * BN;

    {
        int lr = mtile + tid;
        if (lr >= cnt) lr = cnt - 1;
        int p = off + lr;
        sArow[tid] = gather ? g_row_token[p] : p;
    }
    __syncthreads();

    const float* Bg = B0 + (size_t)e * Kd * N + n0;

    // A loader: rows (tid>>1) and (tid>>1)+128, seg (tid&1)*16
    int ar = tid >> 1;
    int aseg = (tid & 1) * 16;
    const float* Ap0 = A + (size_t)sArow[ar] * Kd + aseg;
    const float* Ap1 = A + (size_t)sArow[ar + 128] * Kd + aseg;
    // B loader: rows (tid>>5)+8j, float4 at col (tid&31)*4
    int bk = tid >> 5;
    int bcol = (tid & 31) * 4;
    int bswz = bcol ^ ((bk & 3) << 3);

    float4 raA[2][4], raB[4];
    // prologue: tile 0
    #pragma unroll
    for (int j = 0; j < 4; ++j) {
        raA[0][j] = *(const float4*)(Ap0 + j * 4);
        raA[1][j] = *(const float4*)(Ap1 + j * 4);
        raB[j]    = *(const float4*)(Bg + (size_t)(bk + 8 * j) * N + bcol);
    }
    #pragma unroll
    for (int j = 0; j < 4; ++j) {
        uint4 u0 = make_uint4(f2tf(raA[0][j].x), f2tf(raA[0][j].y), f2tf(raA[0][j].z), f2tf(raA[0][j].w));
        *(uint4*)&AS(0, ar, aseg + j * 4) = u0;
        uint4 u1 = make_uint4(f2tf(raA[1][j].x), f2tf(raA[1][j].y), f2tf(raA[1][j].z), f2tf(raA[1][j].w));
        *(uint4*)&AS(0, ar + 128, aseg + j * 4) = u1;
        uint4 ub = make_uint4(f2tf(raB[j].x), f2tf(raB[j].y), f2tf(raB[j].z), f2tf(raB[j].w));
        *(uint4*)&Bsb[(size_t)(bk + 8 * j) * BN + bswz] = ub;
    }
    __syncthreads();

    int wid = tid >> 5, lane = tid & 31;
    int wm = wid >> 1, wn = wid & 1;     // warp tile: rows wm*64, cols wn*64
    int g = lane >> 2, tg = lane & 3;

    float acc[4][8][4];
    #pragma unroll
    for (int mi = 0; mi < 4; ++mi)
        #pragma unroll
        for (int ni = 0; ni < 8; ++ni)
            #pragma unroll
            for (int c = 0; c < 4; ++c) acc[mi][ni][c] = 0.f;

    int numK = Kd >> 5;
    for (int t = 0; t < numK; ++t) {
        bool has_next = (t + 1 < numK);
        if (has_next) {
            int ko = (t + 1) << 5;
            #pragma unroll
            for (int j = 0; j < 4; ++j) {
                raA[0][j] = *(const float4*)(Ap0 + ko + j * 4);
                raA[1][j] = *(const float4*)(Ap1 + ko + j * 4);
                raB[j]    = *(const float4*)(Bg + (size_t)(ko + bk + 8 * j) * N + bcol);
            }
        }
        int buf = t & 1;
        #pragma unroll
        for (int kk = 0; kk < 4; ++kk) {
            int k8 = kk * 8;
            uint32_t af[4][4];
            #pragma unroll
            for (int mi = 0; mi < 4; ++mi) {
                int r0 = wm * 64 + mi * 16 + g;
                af[mi][0] = AS(buf, r0,     k8 + tg);
                af[mi][1] = AS(buf, r0 + 8, k8 + tg);
                af[mi][2] = AS(buf, r0,     k8 + tg + 4);
                af[mi][3] = AS(buf, r0 + 8, k8 + tg + 4);
            }
            uint32_t bf[8][2];
            #pragma unroll
            for (int ni = 0; ni < 8; ++ni) {
                int nn = wn * 64 + ni * 8 + g;
                bf[ni][0] = BSW(buf, k8 + tg,     nn);
                bf[ni][1] = BSW(buf, k8 + tg + 4, nn);
            }
            #pragma unroll
            for (int mi = 0; mi < 4; ++mi)
                #pragma unroll
                for (int ni = 0; ni < 8; ++ni)
                    mma_tf32(acc[mi][ni], af[mi], bf[ni]);
        }
        if (has_next) {
            int nbuf = buf ^ 1;
            #pragma unroll
            for (int j = 0; j < 4; ++j) {
                uint4 u0 = make_uint4(f2tf(raA[0][j].x), f2tf(raA[0][j].y), f2tf(raA[0][j].z), f2tf(raA[0][j].w));
                *(uint4*)&AS(nbuf, ar, aseg + j * 4) = u0;
                uint4 u1 = make_uint4(f2tf(raA[1][j].x), f2tf(raA[1][j].y), f2tf(raA[1][j].z), f2tf(raA[1][j].w));
                *(uint4*)&AS(nbuf, ar + 128, aseg + j * 4) = u1;
                uint4 ub = make_uint4(f2tf(raB[j].x), f2tf(raB[j].y), f2tf(raB[j].z), f2tf(raB[j].w));
                *(uint4*)&Bsb[(size_t)nbuf * BS_BUF + (size_t)(bk + 8 * j) * BN + bswz] = ub;
            }
            __syncthreads();
        }
    }

    // epilogue
    #pragma unroll
    for (int mi = 0; mi < 4; ++mi) {
        int lr0 = mtile + wm * 64 + mi * 16 + g;
        #pragma unroll
        for (int ni = 0; ni < 8; ++ni) {
            int col = n0 + wn * 64 + ni * 8 + tg * 2;
            if (lr0 < cnt)
                *(float2*)(C + (size_t)(off + lr0) * N + col) =
                    make_float2(acc[mi][ni][0], acc[mi][ni][1]);
            if (lr0 + 8 < cnt)
                *(float2*)(C + (size_t)(off + lr0 + 8) * N + col) =
                    make_float2(acc[mi][ni][2], acc[mi][ni][3]);
        }
    }
#undef AS
#undef BSW
}

// ---------------- SwiGLU elementwise ----------------
__global__ void silu_mul_kernel(float* __restrict__ g, const float* __restrict__ u,
                                long n4)
{
    long i = (long)blockIdx.x * blockDim.x + threadIdx.x;
    long stride = (long)gridDim.x * blockDim.x;
    float4* gv = (float4*)g;
    const float4* uv = (const float4*)u;
    for (; i < n4; i += stride) {
        float4 gg = gv[i];
        float4 uu = uv[i];
        gg.x = gg.x / (1.f + __expf(-gg.x)) * uu.x;
        gg.y = gg.y / (1.f + __expf(-gg.y)) * uu.y;
        gg.z = gg.z / (1.f + __expf(-gg.z)) * uu.z;
        gg.w = gg.w / (1.f + __expf(-gg.w)) * uu.w;
        gv[i] = gg;
    }
}

// ---------------- combine ----------------
__global__ void combine_kernel(const float* __restrict__ down, float* __restrict__ out)
{
    int t = blockIdx.x;
    int tid = threadIdx.x;
    int   pidx[TOPK];
    float pw[TOPK];
    #pragma unroll
    for (int k = 0; k < TOPK; ++k) {
        pidx[k] = g_inv[t * TOPK + k];
        pw[k]   = g_tkw[t * TOPK + k];
    }
    const int H4 = HID / 4;
    float4* ov = (float4*)out;
    const float4* dv = (const float4*)down;
    for (int i = tid; i < H4; i += 256) {
        float4 o = ov[(size_t)t * H4 + i];
        #pragma unroll
        for (int k = 0; k < TOPK; ++k) {
            float4 v = dv[(size_t)pidx[k] * H4 + i];
            float w = pw[k];
            o.x = fmaf(w, v.x, o.x);
            o.y = fmaf(w, v.y, o.y);
            o.z = fmaf(w, v.z, o.z);
            o.w = fmaf(w, v.w, o.w);
        }
        ov[(size_t)t * H4 + i] = o;
    }
}

// ---------------- launch ----------------
static float* symf(const void* sym) {
    void* p = nullptr;
    cudaGetSymbolAddress(&p, sym);
    return (float*)p;
}

extern "C" void kernel_launch(void* const* d_in, const int* in_sizes, int n_in,
                              void* d_out, int out_size)
{
    const float* x       = (const float*)d_in[0];
    const float* rw      = (const float*)d_in[1];
    const float* rbias   = (const float*)d_in[2];
    const float* w_gate  = (const float*)d_in[3];  // [E,H,I] = [E][K][N]
    const float* w_up    = (const float*)d_in[4];
    const float* w_down  = (const float*)d_in[5];  // [E,I,H]
    const float* sw_gate = (const float*)d_in[6];  // [H,SI]
    const float* sw_up   = (const float*)d_in[7];
    const float* sw_down = (const float*)d_in[8];  // [SI,H]
    float* out = (float*)d_out;

    float* p_gate = symf(g_gate);
    float* p_up   = symf(g_up);
    float* p_down = symf(g_down);
    float* p_sg   = symf(g_sg);
    float* p_su   = symf(g_su);

    const int SMB = GEMM_SMEM_W * 4;
    cudaFuncSetAttribute(tmma_kernel, cudaFuncAttributeMaxDynamicSharedMemorySize, SMB);

    // 0) router + dispatch
    router_kernel<<<TOK, 128>>>(x, rw, rbias);
    dispatch_kernel<<<1, 1024>>>();

    // 1) routed gate / up (A gathered from x)
    tmma_kernel<<<dim3(8, 16, NEXP), 256, SMB>>>(x, w_gate, p_gate, IDIM, HID, 1, 1, 0);
    tmma_kernel<<<dim3(8, 16, NEXP), 256, SMB>>>(x, w_up,   p_up,   IDIM, HID, 1, 1, 0);

    // 2) SwiGLU (in place into g_gate)
    silu_mul_kernel<<<2048, 256>>>(p_gate, p_up, (long)NROW * IDIM / 4);

    // 3) routed down
    tmma_kernel<<<dim3(16, 16, NEXP), 256, SMB>>>(p_gate, w_down, p_down, HID, IDIM, 1, 0, 0);

    // 4) shared expert
    tmma_kernel<<<dim3(16, 16, 1), 256, SMB>>>(x, sw_gate, p_sg, SDIM, HID, 0, 0, TOK);
    tmma_kernel<<<dim3(16, 16, 1), 256, SMB>>>(x, sw_up,   p_su, SDIM, HID, 0, 0, TOK);
    silu_mul_kernel<<<2048, 256>>>(p_sg, p_su, (long)TOK * SDIM / 4);
    tmma_kernel<<<dim3(16, 16, 1), 256, SMB>>>(p_sg, sw_down, out, HID, SDIM, 0, 0, TOK);

    // 5) weighted combine
    combine_kernel<<<TOK, 256>>>(p_down, out);
}